// round 1
// baseline (speedup 1.0000x reference)
#include <cuda_runtime.h>
#include <cstdint>

// Problem geometry (fixed by setup_inputs): (16, 4, 1024, 1024) float32
#define BATCH 16
#define HH 1024
#define WW 1024
#define HW (HH * WW)
#define NTOT (BATCH * HW)   // 16,777,216 output elements

// Scratch for intermediate T_new (advection stage) — __device__ global (no alloc).
__device__ float g_T1[NTOT];
// Max |u|,|v| as float bits (all values >= 0, so int compare == float compare).
__device__ unsigned int g_max_bits;

__global__ void reset_kernel() {
    g_max_bits = 0u;
}

// Reduce max(|x|) over channels 0 and 1 of every batch.
// For batch b, floats [b*4*HW, b*4*HW + 2*HW) are u then v (contiguous).
__global__ void maxabs_kernel(const float* __restrict__ in) {
    const long long total4 = (long long)BATCH * 2 * HW / 4;  // float4 count
    float m = 0.0f;
    for (long long i = (long long)blockIdx.x * blockDim.x + threadIdx.x;
         i < total4;
         i += (long long)gridDim.x * blockDim.x) {
        long long e = i * 4;                 // element index within virtual u|v space
        long long b = e / (2LL * HW);
        long long off = e - b * (2LL * HW);
        const float4 vv = *reinterpret_cast<const float4*>(in + b * 4LL * HW + off);
        m = fmaxf(m, fabsf(vv.x));
        m = fmaxf(m, fabsf(vv.y));
        m = fmaxf(m, fabsf(vv.z));
        m = fmaxf(m, fabsf(vv.w));
    }
    // warp reduce
    #pragma unroll
    for (int o = 16; o > 0; o >>= 1)
        m = fmaxf(m, __shfl_xor_sync(0xFFFFFFFFu, m, o));
    __shared__ float smax[32];
    int lane = threadIdx.x & 31;
    int wid = threadIdx.x >> 5;
    if (lane == 0) smax[wid] = m;
    __syncthreads();
    if (wid == 0) {
        int nwarps = (blockDim.x + 31) >> 5;
        m = (lane < nwarps) ? smax[lane] : 0.0f;
        #pragma unroll
        for (int o = 16; o > 0; o >>= 1)
            m = fmaxf(m, __shfl_xor_sync(0xFFFFFFFFu, m, o));
        if (lane == 0)
            atomicMax(&g_max_bits, __float_as_uint(m));
    }
}

__device__ __forceinline__ float compute_dt() {
    const float dx = (float)(1.0 / 126.0);
    float uvmag = __uint_as_float(g_max_bits);
    float dt_advect = 0.5f * 0.1f * dx / uvmag;
    float dx2 = dx * dx;
    float dt_diffuse = 0.5f * (dx2 * dx2) / (dx2 + dx2);
    return fminf(dt_advect, dt_diffuse);
}

// Stage 1: upwind advection.  T1 = T + dt*(-u*dT_dx - v*dT_dy)
__global__ void advect_kernel(const float* __restrict__ in) {
    int idx = blockIdx.x * blockDim.x + threadIdx.x;
    if (idx >= NTOT) return;

    const float dx = (float)(1.0 / 126.0);
    const float dt = compute_dt();

    int x = idx & (WW - 1);
    int y = (idx >> 10) & (HH - 1);
    int b = idx >> 20;

    const float* __restrict__ base = in + (long long)b * 4 * HW;
    const float* __restrict__ U = base;
    const float* __restrict__ V = base + HW;
    const float* __restrict__ T = base + 2 * HW;

    int xm = max(x - 1, 0), xp = min(x + 1, WW - 1);
    int ym = max(y - 1, 0), yp = min(y + 1, HH - 1);

    int row = y * WW;
    float c = T[row + x];
    float l = T[row + xm];
    float r = T[row + xp];
    float t = T[ym * WW + x];
    float d = T[yp * WW + x];

    float u = U[row + x];
    float v = V[row + x];

    float dTl = (c - l) / dx;
    float dTr = (r - c) / dx;
    float dTt = (c - t) / dx;
    float dTb = (d - c) / dx;

    float dTdx = (u > 0.0f) ? dTl : ((u < 0.0f) ? dTr : 0.0f);
    float dTdy = (v > 0.0f) ? dTt : ((v < 0.0f) ? dTb : 0.0f);

    g_T1[idx] = c + dt * (-u * dTdx - v * dTdy);
}

// Stage 2: 9-point Laplacian on T1 (edge-replicated), add RaQ_Ra, write out.
__global__ void laplace_kernel(const float* __restrict__ in,
                               float* __restrict__ out, int out_size) {
    int idx = blockIdx.x * blockDim.x + threadIdx.x;
    if (idx >= NTOT) return;

    const float dx = (float)(1.0 / 126.0);
    const float dt = compute_dt();

    int x = idx & (WW - 1);
    int y = (idx >> 10) & (HH - 1);
    int b = idx >> 20;

    const float* __restrict__ T1 = g_T1 + (long long)b * HW;
    const float* __restrict__ Ra = in + (long long)b * 4 * HW + 3LL * HW;

    int xm = max(x - 1, 0), xp = min(x + 1, WW - 1);
    int ym = max(y - 1, 0), yp = min(y + 1, HH - 1);

    int rm = ym * WW, r0 = y * WW, rp = yp * WW;

    float tl = T1[rm + xm], tc = T1[rm + x], tr = T1[rm + xp];
    float ml = T1[r0 + xm], cc = T1[r0 + x], mr = T1[r0 + xp];
    float bl = T1[rp + xm], bc = T1[rp + x], br = T1[rp + xp];

    float dx2 = dx * dx;
    float lap = 0.25f * (tl + 2.0f * tc + tr
                       + 2.0f * ml - 12.0f * cc + 2.0f * mr
                       + bl + 2.0f * bc + br) / dx2;

    out[idx] = cc + dt * (lap + Ra[r0 + x]);

    if (idx == 0) {
        out[out_size - 1] = dt;  // scalar dt appended after T_new
    }
}

extern "C" void kernel_launch(void* const* d_in, const int* in_sizes, int n_in,
                              void* d_out, int out_size) {
    const float* in = (const float*)d_in[0];
    float* out = (float*)d_out;

    reset_kernel<<<1, 1>>>();

    // reduction over 2*NTOT floats = 8M float4
    maxabs_kernel<<<2048, 256>>>(in);

    const int threads = 256;
    const int blocks = (NTOT + threads - 1) / threads;
    advect_kernel<<<blocks, threads>>>(in);
    laplace_kernel<<<blocks, threads>>>(in, out, out_size);
}

// round 2
// speedup vs baseline: 1.6970x; 1.6970x over previous
#include <cuda_runtime.h>
#include <cstdint>

// Geometry fixed by setup_inputs: (16, 4, 1024, 1024) float32
#define BATCH 16
#define HH 1024
#define WW 1024
#define HW (HH * WW)
#define NTOT (BATCH * HW)

#define TILE_W 128
#define TILE_H 32
#define SMW (TILE_W + 4)      // padded smem row stride (132): 130 used + 2 pad
#define NPTS ((TILE_H + 2) * (TILE_W + 2))   // 34*130 = 4420 T1 points per block

__device__ unsigned int g_max_bits;

__global__ void reset_kernel() { g_max_bits = 0u; }

// max(|u|,|v|) over channels 0,1 of each batch. blockIdx.y = batch.
__global__ void maxabs_kernel(const float* __restrict__ in) {
    const float4* __restrict__ base =
        reinterpret_cast<const float4*>(in + (size_t)blockIdx.y * 4 * HW);
    const int n4 = 2 * HW / 4;  // u and v are contiguous: 524288 float4
    float m = 0.0f;
    for (int i = blockIdx.x * blockDim.x + threadIdx.x; i < n4;
         i += gridDim.x * blockDim.x) {
        float4 vv = base[i];
        m = fmaxf(m, fabsf(vv.x));
        m = fmaxf(m, fabsf(vv.y));
        m = fmaxf(m, fabsf(vv.z));
        m = fmaxf(m, fabsf(vv.w));
    }
    #pragma unroll
    for (int o = 16; o > 0; o >>= 1)
        m = fmaxf(m, __shfl_xor_sync(0xFFFFFFFFu, m, o));
    __shared__ float smax[8];
    int lane = threadIdx.x & 31, wid = threadIdx.x >> 5;
    if (lane == 0) smax[wid] = m;
    __syncthreads();
    if (wid == 0) {
        m = (lane < (blockDim.x >> 5)) ? smax[lane] : 0.0f;
        #pragma unroll
        for (int o = 16; o > 0; o >>= 1)
            m = fmaxf(m, __shfl_xor_sync(0xFFFFFFFFu, m, o));
        if (lane == 0) atomicMax(&g_max_bits, __float_as_uint(m));
    }
}

__device__ __forceinline__ float compute_dt() {
    const float dx = (float)(1.0 / 126.0);
    float uvmag = __uint_as_float(g_max_bits);
    float dt_advect = 0.5f * 0.1f * dx / uvmag;
    float dx2 = dx * dx;
    float dt_diffuse = 0.5f * (dx2 * dx2) / (dx2 + dx2);
    return fminf(dt_advect, dt_diffuse);
}

// Fused: upwind advection (into smem tile w/ 1-halo, halo recomputed) then
// 9-point Laplacian + RaQ term, float4 output.
__global__ __launch_bounds__(256)
void fused_kernel(const float* __restrict__ in, float* __restrict__ out,
                  int out_size) {
    __shared__ float sT1[(TILE_H + 2) * SMW];

    const int tid = threadIdx.x;
    const int x0 = blockIdx.x * TILE_W;
    const int y0 = blockIdx.y * TILE_H;
    const int b  = blockIdx.z;

    const float dx = (float)(1.0 / 126.0);
    const float inv_dx = 1.0f / dx;
    const float dt = compute_dt();

    const float* __restrict__ U  = in + (size_t)b * 4 * HW;
    const float* __restrict__ V  = U + HW;
    const float* __restrict__ T  = U + 2 * HW;
    const float* __restrict__ Ra = U + 3 * HW;

    // ---- Phase 1: advection into smem over (TILE_H+2) x (TILE_W+2) ----
    for (int i = tid; i < NPTS; i += 256) {
        int ly = i / (TILE_W + 2);
        int lx = i - ly * (TILE_W + 2);
        int gy = min(max(y0 - 1 + ly, 0), HH - 1);
        int gx = min(max(x0 - 1 + lx, 0), WW - 1);

        int xm = max(gx - 1, 0), xp = min(gx + 1, WW - 1);
        int ym = max(gy - 1, 0), yp = min(gy + 1, HH - 1);
        int row = gy * WW;

        float c = T[row + gx];
        float l = T[row + xm];
        float r = T[row + xp];
        float t = T[ym * WW + gx];
        float d = T[yp * WW + gx];
        float u = U[row + gx];
        float v = V[row + gx];

        float dTdx = (u > 0.0f) ? (c - l) * inv_dx
                                : ((u < 0.0f) ? (r - c) * inv_dx : 0.0f);
        float dTdy = (v > 0.0f) ? (c - t) * inv_dx
                                : ((v < 0.0f) ? (d - c) * inv_dx : 0.0f);

        sT1[ly * SMW + lx] = c + dt * (-u * dTdx - v * dTdy);
    }
    __syncthreads();

    // ---- Phase 2: 9-pt Laplacian, 4 outputs per quad, float4 I/O ----
    const float dx2 = dx * dx;
    const float lap_scale = 0.25f / dx2;
    // 1024 float4-quads per tile (32 wide x 32 tall), 4 per thread
    #pragma unroll
    for (int k = 0; k < 4; k++) {
        int q = tid + k * 256;
        int qy = q >> 5;          // 0..31 (tile row)
        int qx = (q & 31) << 2;   // 0,4,...,124 (tile col of first pixel)

        const float* s0 = &sT1[qy * SMW + qx];          // row qy   (gy-1)
        const float* s1 = s0 + SMW;                     // row qy+1 (gy)
        const float* s2 = s1 + SMW;                     // row qy+2 (gy+1)

        size_t gidx = (size_t)(y0 + qy) * WW + (x0 + qx);
        float4 ra = *reinterpret_cast<const float4*>(Ra + gidx);

        float4 res;
        #pragma unroll
        for (int j = 0; j < 4; j++) {
            float tl = s0[j],     tc = s0[j + 1], tr = s0[j + 2];
            float ml = s1[j],     cc = s1[j + 1], mr = s1[j + 2];
            float bl = s2[j],     bc = s2[j + 1], br = s2[j + 2];
            float lap = lap_scale *
                (tl + 2.0f * tc + tr +
                 2.0f * ml - 12.0f * cc + 2.0f * mr +
                 bl + 2.0f * bc + br);
            float rr = (&ra.x)[j];
            (&res.x)[j] = cc + dt * (lap + rr);
        }
        *reinterpret_cast<float4*>(out + (size_t)b * HW + gidx) = res;
    }

    if (tid == 0 && blockIdx.x == 0 && blockIdx.y == 0 && blockIdx.z == 0) {
        out[out_size - 1] = dt;
    }
}

extern "C" void kernel_launch(void* const* d_in, const int* in_sizes, int n_in,
                              void* d_out, int out_size) {
    const float* in = (const float*)d_in[0];
    float* out = (float*)d_out;

    reset_kernel<<<1, 1>>>();

    dim3 rgrid(128, BATCH);
    maxabs_kernel<<<rgrid, 256>>>(in);

    dim3 fgrid(WW / TILE_W, HH / TILE_H, BATCH);  // 8 x 32 x 16 = 4096 blocks
    fused_kernel<<<fgrid, 256>>>(in, out, out_size);
}

// round 3
// speedup vs baseline: 1.8657x; 1.0994x over previous
#include <cuda_runtime.h>
#include <cstdint>

// Geometry fixed by setup_inputs: (16, 4, 1024, 1024) float32
#define BATCH 16
#define HH 1024
#define WW 1024
#define HW (HH * WW)
#define NTOT (BATCH * HW)

#define TILE_W 128
#define TILE_H 64
#define THREADS 512
#define SMW (TILE_W + 4)                    // 132: padded smem pitch
#define NPTS ((TILE_H + 2) * (TILE_W + 2))  // 66*130 = 8580 T1 points / block

#define RED_X 128                            // maxabs blocks per batch
#define NPART (RED_X * BATCH)                // 2048 partial maxes

__device__ float g_partials[NPART];

// ---------------------------------------------------------------------------
// Stage 1: per-block max(|u|,|v|) partials. No atomics, no reset needed —
// every slot is written unconditionally every run.
// ---------------------------------------------------------------------------
__global__ __launch_bounds__(256)
void maxabs_kernel(const float* __restrict__ in) {
    const float4* __restrict__ base =
        reinterpret_cast<const float4*>(in + (size_t)blockIdx.y * 4 * HW);
    const int n4 = 2 * HW / 4;  // u,v contiguous: 524288 float4 per batch
    float m = 0.0f;
    #pragma unroll 4
    for (int i = blockIdx.x * 256 + threadIdx.x; i < n4; i += RED_X * 256) {
        float4 vv = base[i];
        m = fmaxf(m, fabsf(vv.x));
        m = fmaxf(m, fabsf(vv.y));
        m = fmaxf(m, fabsf(vv.z));
        m = fmaxf(m, fabsf(vv.w));
    }
    #pragma unroll
    for (int o = 16; o > 0; o >>= 1)
        m = fmaxf(m, __shfl_xor_sync(0xFFFFFFFFu, m, o));
    __shared__ float smax[8];
    int lane = threadIdx.x & 31, wid = threadIdx.x >> 5;
    if (lane == 0) smax[wid] = m;
    __syncthreads();
    if (threadIdx.x == 0) {
        float mm = smax[0];
        #pragma unroll
        for (int w = 1; w < 8; w++) mm = fmaxf(mm, smax[w]);
        g_partials[blockIdx.y * RED_X + blockIdx.x] = mm;
    }
}

// ---------------------------------------------------------------------------
// Stage 2 (fused): final max reduce -> dt; upwind advection into smem tile
// (1-halo, recomputed); 9-pt Laplacian + RaQ; float4 output.
// ---------------------------------------------------------------------------
__global__ __launch_bounds__(THREADS)
void fused_kernel(const float* __restrict__ in, float* __restrict__ out,
                  int out_size) {
    __shared__ float sT1[(TILE_H + 2) * SMW];
    __shared__ float swarp[THREADS / 32];
    __shared__ float s_dt;

    const int tid = threadIdx.x;
    const int x0 = blockIdx.x * TILE_W;
    const int y0 = blockIdx.y * TILE_H;
    const int b  = blockIdx.z;

    // ---- Prologue: reduce 2048 partials (L2-resident) -> dt ----
    {
        float m = 0.0f;
        #pragma unroll
        for (int i = 0; i < NPART / THREADS; i++)
            m = fmaxf(m, g_partials[tid + i * THREADS]);
        #pragma unroll
        for (int o = 16; o > 0; o >>= 1)
            m = fmaxf(m, __shfl_xor_sync(0xFFFFFFFFu, m, o));
        int lane = tid & 31, wid = tid >> 5;
        if (lane == 0) swarp[wid] = m;
        __syncthreads();
        if (tid == 0) {
            float mm = swarp[0];
            #pragma unroll
            for (int w = 1; w < THREADS / 32; w++) mm = fmaxf(mm, swarp[w]);
            const float dx = (float)(1.0 / 126.0);
            float dt_advect = 0.5f * 0.1f * dx / mm;
            float dx2 = dx * dx;
            float dt_diffuse = 0.5f * (dx2 * dx2) / (dx2 + dx2);
            s_dt = fminf(dt_advect, dt_diffuse);
        }
        __syncthreads();
    }
    const float dt = s_dt;

    const float dx = (float)(1.0 / 126.0);
    const float inv_dx = 1.0f / dx;

    const float* __restrict__ U  = in + (size_t)b * 4 * HW;
    const float* __restrict__ V  = U + HW;
    const float* __restrict__ T  = U + 2 * HW;
    const float* __restrict__ Ra = U + 3 * HW;

    // ---- Phase 1: advection over (TILE_H+2) x (TILE_W+2), into smem ----
    #pragma unroll 4
    for (int i = tid; i < NPTS; i += THREADS) {
        int ly = i / (TILE_W + 2);
        int lx = i - ly * (TILE_W + 2);
        int gy = min(max(y0 - 1 + ly, 0), HH - 1);
        int gx = min(max(x0 - 1 + lx, 0), WW - 1);

        int xm = max(gx - 1, 0), xp = min(gx + 1, WW - 1);
        int ym = max(gy - 1, 0), yp = min(gy + 1, HH - 1);
        int row = gy * WW;

        float c = T[row + gx];
        float l = T[row + xm];
        float r = T[row + xp];
        float t = T[ym * WW + gx];
        float d = T[yp * WW + gx];
        float u = U[row + gx];
        float v = V[row + gx];

        float dTdx = (u > 0.0f) ? (c - l) * inv_dx
                                : ((u < 0.0f) ? (r - c) * inv_dx : 0.0f);
        float dTdy = (v > 0.0f) ? (c - t) * inv_dx
                                : ((v < 0.0f) ? (d - c) * inv_dx : 0.0f);

        sT1[ly * SMW + lx] = c + dt * (-u * dTdx - v * dTdy);
    }
    __syncthreads();

    // ---- Phase 2: 9-pt Laplacian, float4-vectorized smem reads + I/O ----
    const float dx2 = dx * dx;
    const float lap_scale = 0.25f / dx2;
    // (TILE_W/4) x TILE_H = 32 x 64 = 2048 quads, 4 per thread
    #pragma unroll
    for (int k = 0; k < (TILE_W / 4) * TILE_H / THREADS; k++) {
        int q = tid + k * THREADS;
        int qy = q >> 5;          // 0..63
        int qx = (q & 31) << 2;   // 0,4,...,124

        const float* s0 = &sT1[qy * SMW + qx];   // row gy-1
        const float* s1 = s0 + SMW;              // row gy
        const float* s2 = s1 + SMW;              // row gy+1

        // 6 contiguous floats per row, float4+float2 (aligned: qx%4==0, SMW%4==0)
        float4 a0 = *reinterpret_cast<const float4*>(s0);
        float2 a1 = *reinterpret_cast<const float2*>(s0 + 4);
        float4 b0 = *reinterpret_cast<const float4*>(s1);
        float2 b1 = *reinterpret_cast<const float2*>(s1 + 4);
        float4 c0 = *reinterpret_cast<const float4*>(s2);
        float2 c1 = *reinterpret_cast<const float2*>(s2 + 4);

        float r0[6] = {a0.x, a0.y, a0.z, a0.w, a1.x, a1.y};
        float r1[6] = {b0.x, b0.y, b0.z, b0.w, b1.x, b1.y};
        float r2[6] = {c0.x, c0.y, c0.z, c0.w, c1.x, c1.y};

        size_t gidx = (size_t)(y0 + qy) * WW + (x0 + qx);
        float4 ra = *reinterpret_cast<const float4*>(Ra + gidx);

        float4 res;
        #pragma unroll
        for (int j = 0; j < 4; j++) {
            float lap = lap_scale *
                (r0[j] + 2.0f * r0[j + 1] + r0[j + 2] +
                 2.0f * r1[j] - 12.0f * r1[j + 1] + 2.0f * r1[j + 2] +
                 r2[j] + 2.0f * r2[j + 1] + r2[j + 2]);
            (&res.x)[j] = r1[j + 1] + dt * (lap + (&ra.x)[j]);
        }
        *reinterpret_cast<float4*>(out + (size_t)b * HW + gidx) = res;
    }

    if (tid == 0 && blockIdx.x == 0 && blockIdx.y == 0 && blockIdx.z == 0) {
        out[out_size - 1] = dt;
    }
}

extern "C" void kernel_launch(void* const* d_in, const int* in_sizes, int n_in,
                              void* d_out, int out_size) {
    const float* in = (const float*)d_in[0];
    float* out = (float*)d_out;

    dim3 rgrid(RED_X, BATCH);
    maxabs_kernel<<<rgrid, 256>>>(in);

    dim3 fgrid(WW / TILE_W, HH / TILE_H, BATCH);  // 8 x 16 x 16 = 2048 blocks
    fused_kernel<<<fgrid, THREADS>>>(in, out, out_size);
}

// round 4
// speedup vs baseline: 1.8964x; 1.0164x over previous
#include <cuda_runtime.h>
#include <cstdint>

// Geometry fixed by setup_inputs: (16, 4, 1024, 1024) float32
#define BATCH 16
#define HH 1024
#define WW 1024
#define HW (HH * WW)
#define NTOT (BATCH * HW)

#define TILE_W 128
#define TILE_H 64
#define THREADS 512
#define SMW (TILE_W + 4)                    // 132: padded smem pitch
#define NPTS ((TILE_H + 2) * (TILE_W + 2))  // 66*130 = 8580 T1 points / block

#define RED_X 128                            // maxabs blocks per batch
#define NPART (RED_X * BATCH)                // 2048 partial maxes

__device__ float g_partials[NPART];

// ---------------------------------------------------------------------------
// Stage 1: per-block max(|u|,|v|) partials. No atomics, no reset needed —
// every slot is written unconditionally every run.
// ---------------------------------------------------------------------------
__global__ __launch_bounds__(256)
void maxabs_kernel(const float* __restrict__ in) {
    const float4* __restrict__ base =
        reinterpret_cast<const float4*>(in + (size_t)blockIdx.y * 4 * HW);
    const int n4 = 2 * HW / 4;  // u,v contiguous: 524288 float4 per batch
    float m = 0.0f;
    #pragma unroll 4
    for (int i = blockIdx.x * 256 + threadIdx.x; i < n4; i += RED_X * 256) {
        float4 vv = base[i];
        m = fmaxf(m, fabsf(vv.x));
        m = fmaxf(m, fabsf(vv.y));
        m = fmaxf(m, fabsf(vv.z));
        m = fmaxf(m, fabsf(vv.w));
    }
    #pragma unroll
    for (int o = 16; o > 0; o >>= 1)
        m = fmaxf(m, __shfl_xor_sync(0xFFFFFFFFu, m, o));
    __shared__ float smax[8];
    int lane = threadIdx.x & 31, wid = threadIdx.x >> 5;
    if (lane == 0) smax[wid] = m;
    __syncthreads();
    if (threadIdx.x == 0) {
        float mm = smax[0];
        #pragma unroll
        for (int w = 1; w < 8; w++) mm = fmaxf(mm, smax[w]);
        g_partials[blockIdx.y * RED_X + blockIdx.x] = mm;
    }
}

// ---------------------------------------------------------------------------
// Stage 2 (fused): final max reduce -> dt; upwind advection into smem tile
// (1-halo, recomputed); 9-pt Laplacian + RaQ; float4 output.
// ---------------------------------------------------------------------------
__global__ __launch_bounds__(THREADS)
void fused_kernel(const float* __restrict__ in, float* __restrict__ out,
                  int out_size) {
    __shared__ float sT1[(TILE_H + 2) * SMW];
    __shared__ float swarp[THREADS / 32];
    __shared__ float s_dt;

    const int tid = threadIdx.x;
    const int x0 = blockIdx.x * TILE_W;
    const int y0 = blockIdx.y * TILE_H;
    const int b  = blockIdx.z;

    // ---- Prologue: reduce 2048 partials (L2-resident) -> dt ----
    {
        float m = 0.0f;
        #pragma unroll
        for (int i = 0; i < NPART / THREADS; i++)
            m = fmaxf(m, g_partials[tid + i * THREADS]);
        #pragma unroll
        for (int o = 16; o > 0; o >>= 1)
            m = fmaxf(m, __shfl_xor_sync(0xFFFFFFFFu, m, o));
        int lane = tid & 31, wid = tid >> 5;
        if (lane == 0) swarp[wid] = m;
        __syncthreads();
        if (tid == 0) {
            float mm = swarp[0];
            #pragma unroll
            for (int w = 1; w < THREADS / 32; w++) mm = fmaxf(mm, swarp[w]);
            const float dx = (float)(1.0 / 126.0);
            float dt_advect = 0.5f * 0.1f * dx / mm;
            float dx2 = dx * dx;
            float dt_diffuse = 0.5f * (dx2 * dx2) / (dx2 + dx2);
            s_dt = fminf(dt_advect, dt_diffuse);
        }
        __syncthreads();
    }
    const float dt = s_dt;

    const float dx = (float)(1.0 / 126.0);
    const float inv_dx = 1.0f / dx;

    const float* __restrict__ U  = in + (size_t)b * 4 * HW;
    const float* __restrict__ V  = U + HW;
    const float* __restrict__ T  = U + 2 * HW;
    const float* __restrict__ Ra = U + 3 * HW;

    // ---- Phase 1: advection over (TILE_H+2) x (TILE_W+2), into smem ----
    #pragma unroll 4
    for (int i = tid; i < NPTS; i += THREADS) {
        int ly = i / (TILE_W + 2);
        int lx = i - ly * (TILE_W + 2);
        int gy = min(max(y0 - 1 + ly, 0), HH - 1);
        int gx = min(max(x0 - 1 + lx, 0), WW - 1);

        int xm = max(gx - 1, 0), xp = min(gx + 1, WW - 1);
        int ym = max(gy - 1, 0), yp = min(gy + 1, HH - 1);
        int row = gy * WW;

        float c = T[row + gx];
        float l = T[row + xm];
        float r = T[row + xp];
        float t = T[ym * WW + gx];
        float d = T[yp * WW + gx];
        float u = U[row + gx];
        float v = V[row + gx];

        float dTdx = (u > 0.0f) ? (c - l) * inv_dx
                                : ((u < 0.0f) ? (r - c) * inv_dx : 0.0f);
        float dTdy = (v > 0.0f) ? (c - t) * inv_dx
                                : ((v < 0.0f) ? (d - c) * inv_dx : 0.0f);

        sT1[ly * SMW + lx] = c + dt * (-u * dTdx - v * dTdy);
    }
    __syncthreads();

    // ---- Phase 2: 9-pt Laplacian, float4-vectorized smem reads + I/O ----
    const float dx2 = dx * dx;
    const float lap_scale = 0.25f / dx2;
    // (TILE_W/4) x TILE_H = 32 x 64 = 2048 quads, 4 per thread
    #pragma unroll
    for (int k = 0; k < (TILE_W / 4) * TILE_H / THREADS; k++) {
        int q = tid + k * THREADS;
        int qy = q >> 5;          // 0..63
        int qx = (q & 31) << 2;   // 0,4,...,124

        const float* s0 = &sT1[qy * SMW + qx];   // row gy-1
        const float* s1 = s0 + SMW;              // row gy
        const float* s2 = s1 + SMW;              // row gy+1

        // 6 contiguous floats per row, float4+float2 (aligned: qx%4==0, SMW%4==0)
        float4 a0 = *reinterpret_cast<const float4*>(s0);
        float2 a1 = *reinterpret_cast<const float2*>(s0 + 4);
        float4 b0 = *reinterpret_cast<const float4*>(s1);
        float2 b1 = *reinterpret_cast<const float2*>(s1 + 4);
        float4 c0 = *reinterpret_cast<const float4*>(s2);
        float2 c1 = *reinterpret_cast<const float2*>(s2 + 4);

        float r0[6] = {a0.x, a0.y, a0.z, a0.w, a1.x, a1.y};
        float r1[6] = {b0.x, b0.y, b0.z, b0.w, b1.x, b1.y};
        float r2[6] = {c0.x, c0.y, c0.z, c0.w, c1.x, c1.y};

        size_t gidx = (size_t)(y0 + qy) * WW + (x0 + qx);
        float4 ra = *reinterpret_cast<const float4*>(Ra + gidx);

        float4 res;
        #pragma unroll
        for (int j = 0; j < 4; j++) {
            float lap = lap_scale *
                (r0[j] + 2.0f * r0[j + 1] + r0[j + 2] +
                 2.0f * r1[j] - 12.0f * r1[j + 1] + 2.0f * r1[j + 2] +
                 r2[j] + 2.0f * r2[j + 1] + r2[j + 2]);
            (&res.x)[j] = r1[j + 1] + dt * (lap + (&ra.x)[j]);
        }
        *reinterpret_cast<float4*>(out + (size_t)b * HW + gidx) = res;
    }

    if (tid == 0 && blockIdx.x == 0 && blockIdx.y == 0 && blockIdx.z == 0) {
        out[out_size - 1] = dt;
    }
}

extern "C" void kernel_launch(void* const* d_in, const int* in_sizes, int n_in,
                              void* d_out, int out_size) {
    const float* in = (const float*)d_in[0];
    float* out = (float*)d_out;

    dim3 rgrid(RED_X, BATCH);
    maxabs_kernel<<<rgrid, 256>>>(in);

    dim3 fgrid(WW / TILE_W, HH / TILE_H, BATCH);  // 8 x 16 x 16 = 2048 blocks
    fused_kernel<<<fgrid, THREADS>>>(in, out, out_size);
}

// round 5
// speedup vs baseline: 1.9555x; 1.0312x over previous
#include <cuda_runtime.h>
#include <cstdint>

// Geometry fixed by setup_inputs: (16, 4, 1024, 1024) float32
#define BATCH 16
#define HH 1024
#define WW 1024
#define HW (HH * WW)

#define TILE_W 128
#define TILE_H 64
#define THREADS 512

// Phase-1 T1 region: rows gy = y0-1 .. y0+64 (66), cols gx = x0-4 .. x0+131
// (34 quads of 4). Pitch 136 floats, float4-aligned.
#define P1ROWS (TILE_H + 2)        // 66
#define QPR 34                     // quads per row
#define SPITCH (QPR * 4)           // 136
#define NQUADS (P1ROWS * QPR)      // 2244

#define RED_X 128
#define NPART (RED_X * BATCH)      // 2048 partials

__device__ float g_partials[NPART];

// ---------------------------------------------------------------------------
// Stage 1: per-block max(|u|,|v|) partials (unconditional writes, no reset).
// ---------------------------------------------------------------------------
__global__ __launch_bounds__(256)
void maxabs_kernel(const float* __restrict__ in) {
    const float4* __restrict__ base =
        reinterpret_cast<const float4*>(in + (size_t)blockIdx.y * 4 * HW);
    const int n4 = 2 * HW / 4;
    float m = 0.0f;
    #pragma unroll 4
    for (int i = blockIdx.x * 256 + threadIdx.x; i < n4; i += RED_X * 256) {
        float4 vv = base[i];
        m = fmaxf(m, fabsf(vv.x));
        m = fmaxf(m, fabsf(vv.y));
        m = fmaxf(m, fabsf(vv.z));
        m = fmaxf(m, fabsf(vv.w));
    }
    #pragma unroll
    for (int o = 16; o > 0; o >>= 1)
        m = fmaxf(m, __shfl_xor_sync(0xFFFFFFFFu, m, o));
    __shared__ float smax[8];
    int lane = threadIdx.x & 31, wid = threadIdx.x >> 5;
    if (lane == 0) smax[wid] = m;
    __syncthreads();
    if (threadIdx.x == 0) {
        float mm = smax[0];
        #pragma unroll
        for (int w = 1; w < 8; w++) mm = fmaxf(mm, smax[w]);
        g_partials[blockIdx.y * RED_X + blockIdx.x] = mm;
    }
}

// ---------------------------------------------------------------------------
// Stage 2 (fused): dt reduce -> vectorized upwind advection into smem
// -> 9-pt Laplacian + RaQ -> float4 out.
// ---------------------------------------------------------------------------
__global__ __launch_bounds__(THREADS)
void fused_kernel(const float* __restrict__ in, float* __restrict__ out,
                  int out_size) {
    __shared__ float sT1[P1ROWS * SPITCH];
    __shared__ float swarp[THREADS / 32];
    __shared__ float s_dt;

    const int tid = threadIdx.x;
    const int x0 = blockIdx.x * TILE_W;
    const int y0 = blockIdx.y * TILE_H;
    const int b  = blockIdx.z;

    // ---- Prologue: reduce partials -> dt ----
    {
        float m = 0.0f;
        #pragma unroll
        for (int i = 0; i < NPART / THREADS; i++)
            m = fmaxf(m, g_partials[tid + i * THREADS]);
        #pragma unroll
        for (int o = 16; o > 0; o >>= 1)
            m = fmaxf(m, __shfl_xor_sync(0xFFFFFFFFu, m, o));
        int lane = tid & 31, wid = tid >> 5;
        if (lane == 0) swarp[wid] = m;
        __syncthreads();
        if (tid == 0) {
            float mm = swarp[0];
            #pragma unroll
            for (int w = 1; w < THREADS / 32; w++) mm = fmaxf(mm, swarp[w]);
            const float dx = (float)(1.0 / 126.0);
            float dt_advect = 0.5f * 0.1f * dx / mm;
            float dx2 = dx * dx;
            float dt_diffuse = 0.5f * (dx2 * dx2) / (dx2 + dx2);
            s_dt = fminf(dt_advect, dt_diffuse);
        }
        __syncthreads();
    }
    const float dt = s_dt;

    const float dx = (float)(1.0 / 126.0);
    const float inv_dx = 1.0f / dx;

    const float* __restrict__ U  = in + (size_t)b * 4 * HW;
    const float* __restrict__ V  = U + HW;
    const float* __restrict__ T  = U + 2 * HW;
    const float* __restrict__ Ra = U + 3 * HW;

    // ---- Phase 1: advection, one float4 quad per iteration ----
    for (int q = tid; q < NQUADS; q += THREADS) {
        int ly = q / QPR;                   // 0..65
        int qi = q - ly * QPR;              // 0..33
        int gx0 = x0 - 4 + (qi << 2);       // quad's first gx (4-aligned)
        int gy = min(max(y0 - 1 + ly, 0), HH - 1);
        int ym = max(gy - 1, 0), yp = min(gy + 1, HH - 1);
        int row = gy * WW;

        float4 res;
        if (gx0 >= 1 && gx0 + 4 <= WW - 1) {
            // Fast path: fully interior in x, all loads vectorized.
            const float4 c4 = *reinterpret_cast<const float4*>(T + row + gx0);
            const float4 t4 = *reinterpret_cast<const float4*>(T + ym * WW + gx0);
            const float4 d4 = *reinterpret_cast<const float4*>(T + yp * WW + gx0);
            const float4 u4 = *reinterpret_cast<const float4*>(U + row + gx0);
            const float4 v4 = *reinterpret_cast<const float4*>(V + row + gx0);
            float cl = T[row + gx0 - 1];
            float cr = T[row + gx0 + 4];

            float L[6] = {cl, c4.x, c4.y, c4.z, c4.w, cr};
            #pragma unroll
            for (int j = 0; j < 4; j++) {
                float c = L[j + 1];
                float u = (&u4.x)[j];
                float v = (&v4.x)[j];
                float t = (&t4.x)[j];
                float d = (&d4.x)[j];
                float dTdx = (u > 0.0f) ? (c - L[j]) * inv_dx
                                        : ((u < 0.0f) ? (L[j + 2] - c) * inv_dx : 0.0f);
                float dTdy = (v > 0.0f) ? (c - t) * inv_dx
                                        : ((v < 0.0f) ? (d - c) * inv_dx : 0.0f);
                (&res.x)[j] = c + dt * (-u * dTdx - v * dTdy);
            }
        } else {
            // Border quad: per-element clamped scalar path.
            #pragma unroll
            for (int j = 0; j < 4; j++) {
                int gx = min(max(gx0 + j, 0), WW - 1);
                int xm = max(gx - 1, 0), xp = min(gx + 1, WW - 1);
                float c = T[row + gx];
                float l = T[row + xm];
                float r = T[row + xp];
                float t = T[ym * WW + gx];
                float d = T[yp * WW + gx];
                float u = U[row + gx];
                float v = V[row + gx];
                float dTdx = (u > 0.0f) ? (c - l) * inv_dx
                                        : ((u < 0.0f) ? (r - c) * inv_dx : 0.0f);
                float dTdy = (v > 0.0f) ? (c - t) * inv_dx
                                        : ((v < 0.0f) ? (d - c) * inv_dx : 0.0f);
                (&res.x)[j] = c + dt * (-u * dTdx - v * dTdy);
            }
        }
        *reinterpret_cast<float4*>(&sT1[ly * SPITCH + (qi << 2)]) = res;
    }
    __syncthreads();

    // ---- Phase 2: 9-pt Laplacian. Output quad ox=qx..qx+3 reads smem
    //      window lx = qx+3 .. qx+8 (center lx = ox+4). 3 aligned LDS.128/row.
    const float dx2 = dx * dx;
    const float lap_scale = 0.25f / dx2;
    #pragma unroll
    for (int k = 0; k < (TILE_W / 4) * TILE_H / THREADS; k++) {
        int q = tid + k * THREADS;
        int qy = q >> 5;          // 0..63
        int qx = (q & 31) << 2;   // 0..124

        const float* s0 = &sT1[qy * SPITCH + qx];        // row gy-1
        const float* s1 = s0 + SPITCH;                   // row gy
        const float* s2 = s1 + SPITCH;                   // row gy+1

        float r0[12], r1[12], r2[12];
        #pragma unroll
        for (int p = 0; p < 3; p++) {
            *reinterpret_cast<float4*>(&r0[p * 4]) =
                *reinterpret_cast<const float4*>(s0 + p * 4);
            *reinterpret_cast<float4*>(&r1[p * 4]) =
                *reinterpret_cast<const float4*>(s1 + p * 4);
            *reinterpret_cast<float4*>(&r2[p * 4]) =
                *reinterpret_cast<const float4*>(s2 + p * 4);
        }

        size_t gidx = (size_t)(y0 + qy) * WW + (x0 + qx);
        float4 ra = *reinterpret_cast<const float4*>(Ra + gidx);

        float4 res;
        #pragma unroll
        for (int j = 0; j < 4; j++) {
            int i0 = j + 3;  // window: lx = qx+3+j .. qx+5+j
            float lap = lap_scale *
                (r0[i0] + 2.0f * r0[i0 + 1] + r0[i0 + 2] +
                 2.0f * r1[i0] - 12.0f * r1[i0 + 1] + 2.0f * r1[i0 + 2] +
                 r2[i0] + 2.0f * r2[i0 + 1] + r2[i0 + 2]);
            (&res.x)[j] = r1[i0 + 1] + dt * (lap + (&ra.x)[j]);
        }
        *reinterpret_cast<float4*>(out + (size_t)b * HW + gidx) = res;
    }

    if (tid == 0 && blockIdx.x == 0 && blockIdx.y == 0 && blockIdx.z == 0) {
        out[out_size - 1] = dt;
    }
}

extern "C" void kernel_launch(void* const* d_in, const int* in_sizes, int n_in,
                              void* d_out, int out_size) {
    const float* in = (const float*)d_in[0];
    float* out = (float*)d_out;

    dim3 rgrid(RED_X, BATCH);
    maxabs_kernel<<<rgrid, 256>>>(in);

    dim3 fgrid(WW / TILE_W, HH / TILE_H, BATCH);  // 8 x 16 x 16 = 2048
    fused_kernel<<<fgrid, THREADS>>>(in, out, out_size);
}

// round 6
// speedup vs baseline: 2.0739x; 1.0605x over previous
#include <cuda_runtime.h>
#include <cstdint>

// Geometry fixed by setup_inputs: (16, 4, 1024, 1024) float32
#define BATCH 16
#define HH 1024
#define WW 1024
#define HW (HH * WW)

#define TILE_W 128
#define TILE_H 64
#define THREADS 512

// Phase-1 T1 region: rows gy = y0-1 .. y0+64 (66), cols gx = x0-4 .. x0+131
// (34 quads of 4). Pitch 136 floats, float4-aligned.
#define P1ROWS (TILE_H + 2)        // 66
#define QPR 34                     // quads per row
#define SPITCH (QPR * 4)           // 136
#define NQUADS (P1ROWS * QPR)      // 2244

#define RED_X 128
#define NPART (RED_X * BATCH)      // 2048 partials

__device__ float g_partials[NPART];

// ---------------------------------------------------------------------------
// Stage 1: per-block max(|u|,|v|) partials (unconditional writes, no reset).
// ---------------------------------------------------------------------------
__global__ __launch_bounds__(256)
void maxabs_kernel(const float* __restrict__ in) {
    const float4* __restrict__ base =
        reinterpret_cast<const float4*>(in + (size_t)blockIdx.y * 4 * HW);
    const int n4 = 2 * HW / 4;
    float m = 0.0f;
    #pragma unroll 8
    for (int i = blockIdx.x * 256 + threadIdx.x; i < n4; i += RED_X * 256) {
        float4 vv = base[i];
        m = fmaxf(m, fabsf(vv.x));
        m = fmaxf(m, fabsf(vv.y));
        m = fmaxf(m, fabsf(vv.z));
        m = fmaxf(m, fabsf(vv.w));
    }
    #pragma unroll
    for (int o = 16; o > 0; o >>= 1)
        m = fmaxf(m, __shfl_xor_sync(0xFFFFFFFFu, m, o));
    __shared__ float smax[8];
    int lane = threadIdx.x & 31, wid = threadIdx.x >> 5;
    if (lane == 0) smax[wid] = m;
    __syncthreads();
    if (threadIdx.x == 0) {
        float mm = smax[0];
        #pragma unroll
        for (int w = 1; w < 8; w++) mm = fmaxf(mm, smax[w]);
        g_partials[blockIdx.y * RED_X + blockIdx.x] = mm;
    }
}

// ---------------------------------------------------------------------------
// Stage 2 (fused): dt reduce -> vectorized upwind advection into smem
// -> row-factored 9-pt Laplacian (vertical strips) + RaQ -> float4 out.
// ---------------------------------------------------------------------------
__global__ __launch_bounds__(THREADS)
void fused_kernel(const float* __restrict__ in, float* __restrict__ out,
                  int out_size) {
    __shared__ float sT1[P1ROWS * SPITCH];
    __shared__ float swarp[THREADS / 32];
    __shared__ float s_dt;

    const int tid = threadIdx.x;
    const int x0 = blockIdx.x * TILE_W;
    const int y0 = blockIdx.y * TILE_H;
    const int b  = blockIdx.z;

    // ---- Prologue: reduce partials -> dt ----
    {
        float m = 0.0f;
        #pragma unroll
        for (int i = 0; i < NPART / THREADS; i++)
            m = fmaxf(m, g_partials[tid + i * THREADS]);
        #pragma unroll
        for (int o = 16; o > 0; o >>= 1)
            m = fmaxf(m, __shfl_xor_sync(0xFFFFFFFFu, m, o));
        int lane = tid & 31, wid = tid >> 5;
        if (lane == 0) swarp[wid] = m;
        __syncthreads();
        if (tid == 0) {
            float mm = swarp[0];
            #pragma unroll
            for (int w = 1; w < THREADS / 32; w++) mm = fmaxf(mm, swarp[w]);
            const float dx = (float)(1.0 / 126.0);
            float dt_advect = 0.5f * 0.1f * dx / mm;
            float dx2 = dx * dx;
            float dt_diffuse = 0.5f * (dx2 * dx2) / (dx2 + dx2);
            s_dt = fminf(dt_advect, dt_diffuse);
        }
        __syncthreads();
    }
    const float dt = s_dt;

    const float dx = (float)(1.0 / 126.0);
    const float inv_dx = 1.0f / dx;

    const float* __restrict__ U  = in + (size_t)b * 4 * HW;
    const float* __restrict__ V  = U + HW;
    const float* __restrict__ T  = U + 2 * HW;
    const float* __restrict__ Ra = U + 3 * HW;

    // ---- Phase 1: advection, one float4 quad per iteration ----
    for (int q = tid; q < NQUADS; q += THREADS) {
        int ly = q / QPR;                   // 0..65
        int qi = q - ly * QPR;              // 0..33
        int gx0 = x0 - 4 + (qi << 2);       // quad's first gx (4-aligned)
        int gy = min(max(y0 - 1 + ly, 0), HH - 1);
        int ym = max(gy - 1, 0), yp = min(gy + 1, HH - 1);
        int row = gy * WW;

        float4 res;
        if (gx0 >= 1 && gx0 + 4 <= WW - 1) {
            const float4 c4 = *reinterpret_cast<const float4*>(T + row + gx0);
            const float4 t4 = *reinterpret_cast<const float4*>(T + ym * WW + gx0);
            const float4 d4 = *reinterpret_cast<const float4*>(T + yp * WW + gx0);
            const float4 u4 = *reinterpret_cast<const float4*>(U + row + gx0);
            const float4 v4 = *reinterpret_cast<const float4*>(V + row + gx0);
            float cl = T[row + gx0 - 1];
            float cr = T[row + gx0 + 4];

            float L[6] = {cl, c4.x, c4.y, c4.z, c4.w, cr};
            #pragma unroll
            for (int j = 0; j < 4; j++) {
                float c = L[j + 1];
                float u = (&u4.x)[j];
                float v = (&v4.x)[j];
                float t = (&t4.x)[j];
                float d = (&d4.x)[j];
                float dTdx = (u > 0.0f) ? (c - L[j]) * inv_dx
                                        : ((u < 0.0f) ? (L[j + 2] - c) * inv_dx : 0.0f);
                float dTdy = (v > 0.0f) ? (c - t) * inv_dx
                                        : ((v < 0.0f) ? (d - c) * inv_dx : 0.0f);
                (&res.x)[j] = c + dt * (-u * dTdx - v * dTdy);
            }
        } else {
            #pragma unroll
            for (int j = 0; j < 4; j++) {
                int gx = min(max(gx0 + j, 0), WW - 1);
                int xm = max(gx - 1, 0), xp = min(gx + 1, WW - 1);
                float c = T[row + gx];
                float l = T[row + xm];
                float r = T[row + xp];
                float t = T[ym * WW + gx];
                float d = T[yp * WW + gx];
                float u = U[row + gx];
                float v = V[row + gx];
                float dTdx = (u > 0.0f) ? (c - l) * inv_dx
                                        : ((u < 0.0f) ? (r - c) * inv_dx : 0.0f);
                float dTdy = (v > 0.0f) ? (c - t) * inv_dx
                                        : ((v < 0.0f) ? (d - c) * inv_dx : 0.0f);
                (&res.x)[j] = c + dt * (-u * dTdx - v * dTdy);
            }
        }
        *reinterpret_cast<float4*>(&sT1[ly * SPITCH + (qi << 2)]) = res;
    }
    __syncthreads();

    // ---- Phase 2: row-factored 9-pt Laplacian, vertical 4-row strips ----
    // lap = H(top) + 2*H(mid) + H(bot) - 16*center, H(row)=x+2y+z per column.
    // Thread (cx,cy): quad col qx=cx*4, output rows qy0..qy0+3; reads smem
    // rows qy0..qy0+5 once each (6 rows for 4 outputs instead of 12).
    {
        const float dx2 = dx * dx;
        const float lap_scale = 0.25f / dx2;
        const int cx = tid & 31;
        const int cy = tid >> 5;          // 0..15
        const int qx = cx << 2;           // 0..124
        const int qy0 = cy << 2;          // 0..60

        // Prefetch Ra for the 4 output rows (independent LDG.128s).
        float4 ra[4];
        #pragma unroll
        for (int r = 0; r < 4; r++)
            ra[r] = *reinterpret_cast<const float4*>(
                Ra + (size_t)(y0 + qy0 + r) * WW + (x0 + qx));

        float* outb = out + (size_t)b * HW;

        float h_m2[4], h_m1[4], c_m1[4];
        #pragma unroll
        for (int i = 0; i < 6; i++) {
            const float* s = &sT1[(qy0 + i) * SPITCH + qx];
            float rr[12];
            *reinterpret_cast<float4*>(&rr[0]) =
                *reinterpret_cast<const float4*>(s);
            *reinterpret_cast<float4*>(&rr[4]) =
                *reinterpret_cast<const float4*>(s + 4);
            *reinterpret_cast<float4*>(&rr[8]) =
                *reinterpret_cast<const float4*>(s + 8);

            float h[4], c[4];
            #pragma unroll
            for (int jj = 0; jj < 4; jj++) {
                h[jj] = rr[jj + 3] + 2.0f * rr[jj + 4] + rr[jj + 5];
                c[jj] = rr[jj + 4];
            }

            if (i >= 2) {
                int oy = qy0 + i - 2;
                float4 res;
                #pragma unroll
                for (int jj = 0; jj < 4; jj++) {
                    float lap = h_m2[jj] + 2.0f * h_m1[jj] + h[jj]
                              - 16.0f * c_m1[jj];
                    (&res.x)[jj] = c_m1[jj]
                        + dt * (lap_scale * lap + (&ra[i - 2].x)[jj]);
                }
                *reinterpret_cast<float4*>(
                    outb + (size_t)(y0 + oy) * WW + (x0 + qx)) = res;
            }
            #pragma unroll
            for (int jj = 0; jj < 4; jj++) {
                h_m2[jj] = h_m1[jj];
                h_m1[jj] = h[jj];
                c_m1[jj] = c[jj];
            }
        }
    }

    if (tid == 0 && blockIdx.x == 0 && blockIdx.y == 0 && blockIdx.z == 0) {
        out[out_size - 1] = dt;
    }
}

extern "C" void kernel_launch(void* const* d_in, const int* in_sizes, int n_in,
                              void* d_out, int out_size) {
    const float* in = (const float*)d_in[0];
    float* out = (float*)d_out;

    dim3 rgrid(RED_X, BATCH);
    maxabs_kernel<<<rgrid, 256>>>(in);

    dim3 fgrid(WW / TILE_W, HH / TILE_H, BATCH);  // 8 x 16 x 16 = 2048
    fused_kernel<<<fgrid, THREADS>>>(in, out, out_size);
}

// round 7
// speedup vs baseline: 2.0746x; 1.0004x over previous
#include <cuda_runtime.h>
#include <cstdint>

// Geometry fixed by setup_inputs: (16, 4, 1024, 1024) float32
#define BATCH 16
#define HH 1024
#define WW 1024
#define HW (HH * WW)

#define TILE_W 128
#define TILE_H 64
#define THREADS 512

// Phase-1 T1 region: rows gy = y0-1 .. y0+64 (66), cols gx = x0-4 .. x0+131
// (34 quads of 4). Pitch 136 floats, float4-aligned.
#define P1ROWS (TILE_H + 2)        // 66
#define QPR 34                     // quads per row
#define SPITCH (QPR * 4)           // 136
#define NQUADS (P1ROWS * QPR)      // 2244

#define RED_X 128
#define NPART (RED_X * BATCH)      // 2048 partials

__device__ float g_partials[NPART];

// ---------------------------------------------------------------------------
// Stage 1: per-block max(|u|,|v|) partials (unconditional writes, no reset).
// ---------------------------------------------------------------------------
__global__ __launch_bounds__(256)
void maxabs_kernel(const float* __restrict__ in) {
    const float4* __restrict__ base =
        reinterpret_cast<const float4*>(in + (size_t)blockIdx.y * 4 * HW);
    const int n4 = 2 * HW / 4;
    float m = 0.0f;
    #pragma unroll 8
    for (int i = blockIdx.x * 256 + threadIdx.x; i < n4; i += RED_X * 256) {
        float4 vv = base[i];
        m = fmaxf(m, fabsf(vv.x));
        m = fmaxf(m, fabsf(vv.y));
        m = fmaxf(m, fabsf(vv.z));
        m = fmaxf(m, fabsf(vv.w));
    }
    #pragma unroll
    for (int o = 16; o > 0; o >>= 1)
        m = fmaxf(m, __shfl_xor_sync(0xFFFFFFFFu, m, o));
    __shared__ float smax[8];
    int lane = threadIdx.x & 31, wid = threadIdx.x >> 5;
    if (lane == 0) smax[wid] = m;
    __syncthreads();
    if (threadIdx.x == 0) {
        float mm = smax[0];
        #pragma unroll
        for (int w = 1; w < 8; w++) mm = fmaxf(mm, smax[w]);
        g_partials[blockIdx.y * RED_X + blockIdx.x] = mm;
    }
}

// ---------------------------------------------------------------------------
// Stage 2 (fused): dt reduce -> vectorized upwind advection into smem
// -> row-factored 9-pt Laplacian (vertical strips) + RaQ -> float4 out.
// ---------------------------------------------------------------------------
__global__ __launch_bounds__(THREADS)
void fused_kernel(const float* __restrict__ in, float* __restrict__ out,
                  int out_size) {
    __shared__ float sT1[P1ROWS * SPITCH];
    __shared__ float swarp[THREADS / 32];
    __shared__ float s_dt;

    const int tid = threadIdx.x;
    const int x0 = blockIdx.x * TILE_W;
    const int y0 = blockIdx.y * TILE_H;
    const int b  = blockIdx.z;

    // ---- Prologue: reduce partials -> dt ----
    {
        float m = 0.0f;
        #pragma unroll
        for (int i = 0; i < NPART / THREADS; i++)
            m = fmaxf(m, g_partials[tid + i * THREADS]);
        #pragma unroll
        for (int o = 16; o > 0; o >>= 1)
            m = fmaxf(m, __shfl_xor_sync(0xFFFFFFFFu, m, o));
        int lane = tid & 31, wid = tid >> 5;
        if (lane == 0) swarp[wid] = m;
        __syncthreads();
        if (tid == 0) {
            float mm = swarp[0];
            #pragma unroll
            for (int w = 1; w < THREADS / 32; w++) mm = fmaxf(mm, swarp[w]);
            const float dx = (float)(1.0 / 126.0);
            float dt_advect = 0.5f * 0.1f * dx / mm;
            float dx2 = dx * dx;
            float dt_diffuse = 0.5f * (dx2 * dx2) / (dx2 + dx2);
            s_dt = fminf(dt_advect, dt_diffuse);
        }
        __syncthreads();
    }
    const float dt = s_dt;

    const float dx = (float)(1.0 / 126.0);
    const float inv_dx = 1.0f / dx;

    const float* __restrict__ U  = in + (size_t)b * 4 * HW;
    const float* __restrict__ V  = U + HW;
    const float* __restrict__ T  = U + 2 * HW;
    const float* __restrict__ Ra = U + 3 * HW;

    // ---- Phase 1: advection, one float4 quad per iteration ----
    for (int q = tid; q < NQUADS; q += THREADS) {
        int ly = q / QPR;                   // 0..65
        int qi = q - ly * QPR;              // 0..33
        int gx0 = x0 - 4 + (qi << 2);       // quad's first gx (4-aligned)
        int gy = min(max(y0 - 1 + ly, 0), HH - 1);
        int ym = max(gy - 1, 0), yp = min(gy + 1, HH - 1);
        int row = gy * WW;

        float4 res;
        if (gx0 >= 1 && gx0 + 4 <= WW - 1) {
            const float4 c4 = *reinterpret_cast<const float4*>(T + row + gx0);
            const float4 t4 = *reinterpret_cast<const float4*>(T + ym * WW + gx0);
            const float4 d4 = *reinterpret_cast<const float4*>(T + yp * WW + gx0);
            const float4 u4 = *reinterpret_cast<const float4*>(U + row + gx0);
            const float4 v4 = *reinterpret_cast<const float4*>(V + row + gx0);
            float cl = T[row + gx0 - 1];
            float cr = T[row + gx0 + 4];

            float L[6] = {cl, c4.x, c4.y, c4.z, c4.w, cr};
            #pragma unroll
            for (int j = 0; j < 4; j++) {
                float c = L[j + 1];
                float u = (&u4.x)[j];
                float v = (&v4.x)[j];
                float t = (&t4.x)[j];
                float d = (&d4.x)[j];
                float dTdx = (u > 0.0f) ? (c - L[j]) * inv_dx
                                        : ((u < 0.0f) ? (L[j + 2] - c) * inv_dx : 0.0f);
                float dTdy = (v > 0.0f) ? (c - t) * inv_dx
                                        : ((v < 0.0f) ? (d - c) * inv_dx : 0.0f);
                (&res.x)[j] = c + dt * (-u * dTdx - v * dTdy);
            }
        } else {
            #pragma unroll
            for (int j = 0; j < 4; j++) {
                int gx = min(max(gx0 + j, 0), WW - 1);
                int xm = max(gx - 1, 0), xp = min(gx + 1, WW - 1);
                float c = T[row + gx];
                float l = T[row + xm];
                float r = T[row + xp];
                float t = T[ym * WW + gx];
                float d = T[yp * WW + gx];
                float u = U[row + gx];
                float v = V[row + gx];
                float dTdx = (u > 0.0f) ? (c - l) * inv_dx
                                        : ((u < 0.0f) ? (r - c) * inv_dx : 0.0f);
                float dTdy = (v > 0.0f) ? (c - t) * inv_dx
                                        : ((v < 0.0f) ? (d - c) * inv_dx : 0.0f);
                (&res.x)[j] = c + dt * (-u * dTdx - v * dTdy);
            }
        }
        *reinterpret_cast<float4*>(&sT1[ly * SPITCH + (qi << 2)]) = res;
    }
    __syncthreads();

    // ---- Phase 2: row-factored 9-pt Laplacian, vertical 4-row strips ----
    // lap = H(top) + 2*H(mid) + H(bot) - 16*center, H(row)=x+2y+z per column.
    // Thread (cx,cy): quad col qx=cx*4, output rows qy0..qy0+3; reads smem
    // rows qy0..qy0+5 once each (6 rows for 4 outputs instead of 12).
    {
        const float dx2 = dx * dx;
        const float lap_scale = 0.25f / dx2;
        const int cx = tid & 31;
        const int cy = tid >> 5;          // 0..15
        const int qx = cx << 2;           // 0..124
        const int qy0 = cy << 2;          // 0..60

        // Prefetch Ra for the 4 output rows (independent LDG.128s).
        float4 ra[4];
        #pragma unroll
        for (int r = 0; r < 4; r++)
            ra[r] = *reinterpret_cast<const float4*>(
                Ra + (size_t)(y0 + qy0 + r) * WW + (x0 + qx));

        float* outb = out + (size_t)b * HW;

        float h_m2[4], h_m1[4], c_m1[4];
        #pragma unroll
        for (int i = 0; i < 6; i++) {
            const float* s = &sT1[(qy0 + i) * SPITCH + qx];
            float rr[12];
            *reinterpret_cast<float4*>(&rr[0]) =
                *reinterpret_cast<const float4*>(s);
            *reinterpret_cast<float4*>(&rr[4]) =
                *reinterpret_cast<const float4*>(s + 4);
            *reinterpret_cast<float4*>(&rr[8]) =
                *reinterpret_cast<const float4*>(s + 8);

            float h[4], c[4];
            #pragma unroll
            for (int jj = 0; jj < 4; jj++) {
                h[jj] = rr[jj + 3] + 2.0f * rr[jj + 4] + rr[jj + 5];
                c[jj] = rr[jj + 4];
            }

            if (i >= 2) {
                int oy = qy0 + i - 2;
                float4 res;
                #pragma unroll
                for (int jj = 0; jj < 4; jj++) {
                    float lap = h_m2[jj] + 2.0f * h_m1[jj] + h[jj]
                              - 16.0f * c_m1[jj];
                    (&res.x)[jj] = c_m1[jj]
                        + dt * (lap_scale * lap + (&ra[i - 2].x)[jj]);
                }
                *reinterpret_cast<float4*>(
                    outb + (size_t)(y0 + oy) * WW + (x0 + qx)) = res;
            }
            #pragma unroll
            for (int jj = 0; jj < 4; jj++) {
                h_m2[jj] = h_m1[jj];
                h_m1[jj] = h[jj];
                c_m1[jj] = c[jj];
            }
        }
    }

    if (tid == 0 && blockIdx.x == 0 && blockIdx.y == 0 && blockIdx.z == 0) {
        out[out_size - 1] = dt;
    }
}

extern "C" void kernel_launch(void* const* d_in, const int* in_sizes, int n_in,
                              void* d_out, int out_size) {
    const float* in = (const float*)d_in[0];
    float* out = (float*)d_out;

    dim3 rgrid(RED_X, BATCH);
    maxabs_kernel<<<rgrid, 256>>>(in);

    dim3 fgrid(WW / TILE_W, HH / TILE_H, BATCH);  // 8 x 16 x 16 = 2048
    fused_kernel<<<fgrid, THREADS>>>(in, out, out_size);
}